// round 8
// baseline (speedup 1.0000x reference)
#include <cuda_runtime.h>
#include <cstdint>

#define N_DIM   256
#define BS      256
#define TMAX    1000
#define STEP_F  0.01f
#define EPS_F   0.001f

#define CPC     2                 // batch columns per CTA
#define GRID    (BS / CPC)        // 128 CTAs, 1 per SM
#define THREADS 512               // 16 warps -> 4 warps/SMSP

// Warp (wr = w&7, wk = w>>3): rows [wr*32, wr*32+32), K-half [wk*128, wk*128+128).
// Lane l: rg = l>>3 (0..3), kl = l&7 -> K slice wk*128 + kl*16 .. +16 (4 float4 chunks).
// Thread rows: wr*32 + rg*8 + i, i in [0,8). i<4 -> A in registers, i>=4 -> A in smem.
// After the 8-lane butterfly, lane l owns rows wr*32 + l (both cols, own K-half).
// Cross-K-half combine via sRed; warp (wr,wk) finishes col wk for rows wr*32+l.

#define SA_F4      8192                    // 128 KB of A in smem
#define SX_FLOATS  (2 * 2 * 256)           // double-buffered x, 2 cols, permuted
#define SRED_F2    (2 * 8 * 32)            // partials exchange [wk][wr][lane] float2
#define SMEM_BYTES (SA_F4 * 16 + SX_FLOATS * 4 + SRED_F2 * 8)

union F4 { float4 v; float2 h[2]; };

__device__ __forceinline__ void fma2(float2& d, const float2& a, const float2& b) {
    asm("fma.rn.f32x2 %0, %1, %2, %0;"
        : "+l"(reinterpret_cast<unsigned long long&>(d))
        : "l"(reinterpret_cast<const unsigned long long&>(a)),
          "l"(reinterpret_cast<const unsigned long long&>(b)));
}

// k bits [7]=wk [6:4]=kl [3:2]=j [1:0]=e  ->  p bits [7]=wk [6:5]=j [4:2]=kl [1:0]=e
__device__ __forceinline__ int permx(int k) {
    return (k & 0x80) | ((k & 0x0C) << 3) | ((k & 0x70) >> 2) | (k & 3);
}

__device__ __forceinline__ float a_elem(const float* __restrict__ W, int r, int k) {
    if (k > r) return  __ldg(&W[r * N_DIM + k]);
    if (k < r) return -__ldg(&W[k * N_DIM + r]);
    return -EPS_F;
}

// Accurate fast tanh: tanh(|y|) = 1 - 2/(exp(2|y|)+1)  (abs err ~1e-7)
__device__ __forceinline__ float fast_tanh(float y) {
    float ay = fabsf(y);
    float e;
    asm("ex2.approx.f32 %0, %1;" : "=f"(e) : "f"(ay * 2.8853900817779268f)); // 2*log2(e)
    float r;
    asm("rcp.approx.f32 %0, %1;" : "=f"(r) : "f"(e + 1.0f));
    float t = fmaf(-2.0f, r, 1.0f);
    return copysignf(t, y);
}

// Butterfly reduce-scatter over 8-lane group: v[8] -> lane kl owns sum of v[kl].
__device__ __forceinline__ float reduce8(float* v, int kl) {
    {   bool hi = (kl & 4) != 0;
        #pragma unroll
        for (int i = 0; i < 4; i++) {
            float send = hi ? v[i] : v[i + 4];
            float recv = __shfl_xor_sync(0xffffffffu, send, 4);
            v[i] = (hi ? v[i + 4] : v[i]) + recv;
        }
    }
    {   bool hi = (kl & 2) != 0;
        #pragma unroll
        for (int i = 0; i < 2; i++) {
            float send = hi ? v[i] : v[i + 2];
            float recv = __shfl_xor_sync(0xffffffffu, send, 2);
            v[i] = (hi ? v[i + 2] : v[i]) + recv;
        }
    }
    {   bool hi = (kl & 1) != 0;
        float send = hi ? v[0] : v[1];
        float recv = __shfl_xor_sync(0xffffffffu, send, 1);
        return (hi ? v[1] : v[0]) + recv;
    }
}

extern "C" __global__ void __launch_bounds__(THREADS, 1)
antisym_rnn_kernel(const float* __restrict__ X0,
                   const float* __restrict__ W,
                   const float* __restrict__ by,
                   float* __restrict__ out)
{
    extern __shared__ float smem[];
    float4* sA   = reinterpret_cast<float4*>(smem);         // [8192] f4
    float*  sX   = smem + SA_F4 * 4;                        // [2][2][256] permuted
    float2* sRed = reinterpret_cast<float2*>(sX + SX_FLOATS); // [2][8][32]

    const int tid = threadIdx.x;
    const int w   = tid >> 5;
    const int l   = tid & 31;
    const int wr  = w & 7;             // row block
    const int wk  = w >> 3;            // K half
    const int rg  = l >> 3;            // row-group 0..3
    const int kl  = l & 7;             // K-lane within half
    const int col0 = blockIdx.x * CPC;
    const int row_base = wr * 32 + rg * 8;          // thread's 8 rows start here
    const int k_base   = wk * 128 + kl * 16;        // thread's 16-wide K slice
    const int my_row   = wr * 32 + l;               // row owned after butterfly

    // ---- one-time init: A ----
    float4 areg[4][4];                 // rows i=0..3, K chunks j=0..3
    #pragma unroll
    for (int i = 0; i < 4; i++) {
        int r = row_base + i;
        #pragma unroll
        for (int j = 0; j < 4; j++) {
            int k = k_base + j * 4;
            areg[i][j] = make_float4(a_elem(W, r, k),     a_elem(W, r, k + 1),
                                     a_elem(W, r, k + 2), a_elem(W, r, k + 3));
        }
    }
    #pragma unroll
    for (int i2 = 0; i2 < 4; i2++) {
        int r = row_base + 4 + i2;
        #pragma unroll
        for (int j = 0; j < 4; j++) {
            int k = k_base + j * 4;
            sA[((i2 * 4 + j) * 16 + w) * 32 + l] =
                make_float4(a_elem(W, r, k),     a_elem(W, r, k + 1),
                            a_elem(W, r, k + 2), a_elem(W, r, k + 3));
        }
    }
    const float byv = by[my_row];

    // x0: permuted smem + t=0 output; lane's own (row, col=wk) state in register
    {
        int c  = tid >> 8;
        int rr = tid & 255;
        float v = X0[(col0 + c) * N_DIM + rr];
        sX[(0 * 2 + c) * 256 + permx(rr)] = v;
        out[(size_t)(col0 + c) * (TMAX * N_DIM) + rr] = v;
    }
    float xr = X0[(col0 + wk) * N_DIM + my_row];
    __syncthreads();

    int buf = 0;
    for (int t = 1; t < TMAX; ++t) {
        // f4 base of this thread's K-half for each column
        const float4* xa_p = reinterpret_cast<const float4*>(sX + (buf * 2 + 0) * 256) + wk * 32;
        const float4* xb_p = reinterpret_cast<const float4*>(sX + (buf * 2 + 1) * 256) + wk * 32;

        float2 acc[8][2];
        #pragma unroll
        for (int i = 0; i < 8; i++) { acc[i][0] = make_float2(0.f, 0.f);
                                      acc[i][1] = make_float2(0.f, 0.f); }

        #pragma unroll
        for (int j = 0; j < 4; j++) {
            F4 xa; xa.v = xa_p[j * 8 + kl];
            F4 xb; xb.v = xb_p[j * 8 + kl];
            #pragma unroll
            for (int i = 0; i < 4; i++) {
                F4 a; a.v = areg[i][j];
                fma2(acc[i][0], a.h[0], xa.h[0]); fma2(acc[i][0], a.h[1], xa.h[1]);
                fma2(acc[i][1], a.h[0], xb.h[0]); fma2(acc[i][1], a.h[1], xb.h[1]);
            }
            #pragma unroll
            for (int i2 = 0; i2 < 4; i2++) {
                F4 a; a.v = sA[((i2 * 4 + j) * 16 + w) * 32 + l];
                fma2(acc[4 + i2][0], a.h[0], xa.h[0]); fma2(acc[4 + i2][0], a.h[1], xa.h[1]);
                fma2(acc[4 + i2][1], a.h[0], xb.h[0]); fma2(acc[4 + i2][1], a.h[1], xb.h[1]);
            }
        }

        float v0[8], v1[8];
        #pragma unroll
        for (int i = 0; i < 8; i++) {
            v0[i] = acc[i][0].x + acc[i][0].y;
            v1[i] = acc[i][1].x + acc[i][1].y;
        }

        // lane l ends owning rows wr*32+l: partial (own K-half) for both cols
        float p0 = reduce8(v0, kl);
        float p1 = reduce8(v1, kl);

        // exchange K-half partials
        sRed[(wk * 8 + wr) * 32 + l] = make_float2(p0, p1);
        __syncthreads();
        float2 oth = sRed[((1 - wk) * 8 + wr) * 32 + l];

        float own = wk ? p1 : p0;
        float opp = wk ? oth.y : oth.x;
        float y = own + opp + byv;

        float xn = xr + STEP_F * fast_tanh(y);
        xr = xn;

        const int nbuf = buf ^ 1;
        sX[(nbuf * 2 + wk) * 256 + permx(my_row)] = xn;
        out[(size_t)(col0 + wk) * (TMAX * N_DIM) + (size_t)t * N_DIM + my_row] = xn;

        __syncthreads();
        buf = nbuf;
    }
}

extern "C" void kernel_launch(void* const* d_in, const int* in_sizes, int n_in,
                              void* d_out, int out_size) {
    const float* X0 = (const float*)d_in[0];
    const float* W  = (const float*)d_in[1];
    const float* by = (const float*)d_in[2];
    float* out = (float*)d_out;

    cudaFuncSetAttribute(antisym_rnn_kernel,
                         cudaFuncAttributeMaxDynamicSharedMemorySize, SMEM_BYTES);
    antisym_rnn_kernel<<<GRID, THREADS, SMEM_BYTES>>>(X0, W, by, out);
}

// round 10
// speedup vs baseline: 1.8053x; 1.8053x over previous
#include <cuda_runtime.h>
#include <cstdint>

#define N_DIM   256
#define BS      256
#define TMAX    1000
#define STEP_F  0.01f
#define EPS_F   0.001f

#define CPC     2                 // batch columns per CTA
#define GRID    (BS / CPC)        // 128 CTAs
#define THREADS 256               // 8 warps

// Per-warp layout (same as R3): warp w owns rows [w*32, w*32+32).
// Lane l: rg = l>>3 (row-group 0..3), kl = l&7 (K-slice [kl*32, kl*32+32)).
// Thread rows: w*32 + rg*8 + i, i in [0,8). i<4 -> A in registers, i>=4 -> A in smem.
// After the 8-lane butterfly reduction lane l owns row w*32 + l.

#define SA_F4      8192           // 128 KB of A in smem
#define SX_FLOATS  (2 * 2 * 256)  // double-buffered x, 2 columns, permuted layout
#define SMEM_BYTES (SA_F4 * 16 + SX_FLOATS * 4)

union F4 { float4 v; float2 h[2]; };

__device__ __forceinline__ void fma2(float2& d, const float2& a, const float2& b) {
    asm("fma.rn.f32x2 %0, %1, %2, %0;"
        : "+l"(reinterpret_cast<unsigned long long&>(d))
        : "l"(reinterpret_cast<const unsigned long long&>(a)),
          "l"(reinterpret_cast<const unsigned long long&>(b)));
}

__device__ __forceinline__ int permx(int k) {
    // k = (kl<<5) | (j<<2) | e  ->  (j<<5) | (kl<<2) | e
    return (((k >> 2) & 7) << 5) | ((k >> 5) << 2) | (k & 3);
}

__device__ __forceinline__ float a_elem(const float* __restrict__ W, int r, int k) {
    if (k > r) return  __ldg(&W[r * N_DIM + k]);
    if (k < r) return -__ldg(&W[k * N_DIM + r]);
    return -EPS_F;
}

// Accurate fast tanh: tanh(|y|) = 1 - 2/(exp(2|y|)+1)  (abs err ~1e-7)
__device__ __forceinline__ float fast_tanh(float y) {
    float ay = fabsf(y);
    float e;
    asm("ex2.approx.f32 %0, %1;" : "=f"(e) : "f"(ay * 2.8853900817779268f)); // 2*log2(e)
    float r;
    asm("rcp.approx.f32 %0, %1;" : "=f"(r) : "f"(e + 1.0f));
    float t = fmaf(-2.0f, r, 1.0f);
    return copysignf(t, y);
}

// Butterfly reduce-scatter over 8-lane group: v[8] -> lane kl owns sum of v[kl].
__device__ __forceinline__ float reduce8(float* v, int kl) {
    {   bool hi = (kl & 4) != 0;
        #pragma unroll
        for (int i = 0; i < 4; i++) {
            float send = hi ? v[i] : v[i + 4];
            float recv = __shfl_xor_sync(0xffffffffu, send, 4);
            v[i] = (hi ? v[i + 4] : v[i]) + recv;
        }
    }
    {   bool hi = (kl & 2) != 0;
        #pragma unroll
        for (int i = 0; i < 2; i++) {
            float send = hi ? v[i] : v[i + 2];
            float recv = __shfl_xor_sync(0xffffffffu, send, 2);
            v[i] = (hi ? v[i + 2] : v[i]) + recv;
        }
    }
    {   bool hi = (kl & 1) != 0;
        float send = hi ? v[0] : v[1];
        float recv = __shfl_xor_sync(0xffffffffu, send, 1);
        return (hi ? v[1] : v[0]) + recv;
    }
}

extern "C" __global__ void __launch_bounds__(THREADS, 1)
antisym_rnn_kernel(const float* __restrict__ X0,
                   const float* __restrict__ W,
                   const float* __restrict__ by,
                   float* __restrict__ out)
{
    extern __shared__ float smem[];
    float4* sA = reinterpret_cast<float4*>(smem);           // [8192] f4
    float*  sX = smem + SA_F4 * 4;                          // [2][2][256] permuted

    const int tid = threadIdx.x;
    const int w   = tid >> 5;          // warp 0..7
    const int l   = tid & 31;          // lane
    const int rg  = l >> 3;            // row-group 0..3
    const int kl  = l & 7;             // K-lane 0..7
    const int col0 = blockIdx.x * CPC;
    const int row_base = w * 32 + rg * 8;   // this thread's 8 rows start here
    const int k_base   = kl * 32;           // this thread's K slice
    const int my_row   = w * 32 + l;        // row this lane owns after reduction

    // ---- one-time init ----
    float4 areg[4][8];
    #pragma unroll
    for (int i = 0; i < 4; i++) {
        int r = row_base + i;
        #pragma unroll
        for (int j = 0; j < 8; j++) {
            int k = k_base + j * 4;
            areg[i][j] = make_float4(a_elem(W, r, k),     a_elem(W, r, k + 1),
                                     a_elem(W, r, k + 2), a_elem(W, r, k + 3));
        }
    }
    #pragma unroll
    for (int i4 = 0; i4 < 4; i4++) {
        int r = row_base + 4 + i4;
        #pragma unroll
        for (int j = 0; j < 8; j++) {
            int k = k_base + j * 4;
            sA[((i4 * 8 + j) * 8 + w) * 32 + l] =
                make_float4(a_elem(W, r, k),     a_elem(W, r, k + 1),
                            a_elem(W, r, k + 2), a_elem(W, r, k + 3));
        }
    }
    const float byv = by[my_row];

    // x0 into permuted smem + t=0 output; lane's own-row values in registers
    #pragma unroll
    for (int c = 0; c < CPC; c++) {
        float v = X0[(col0 + c) * N_DIM + tid];
        sX[(0 * 2 + c) * 256 + permx(tid)] = v;
        out[(size_t)(col0 + c) * (TMAX * N_DIM) + tid] = v;
    }
    float xr0 = X0[(col0 + 0) * N_DIM + my_row];
    float xr1 = X0[(col0 + 1) * N_DIM + my_row];
    __syncthreads();

    // ---- A-smem prefetch prologue: chunk j=0 for the 4 smem rows ----
    F4 pA[4];
    #pragma unroll
    for (int i4 = 0; i4 < 4; i4++)
        pA[i4].v = sA[((i4 * 8 + 0) * 8 + w) * 32 + l];

    int buf = 0;
    for (int t = 1; t < TMAX; ++t) {
        const float4* x0p = reinterpret_cast<const float4*>(sX + (buf * 2 + 0) * 256);
        const float4* x1p = reinterpret_cast<const float4*>(sX + (buf * 2 + 1) * 256);

        // hoisted output stores of step t-1 (overlap with this step's matvec)
        if (t > 1) {
            size_t tb = (size_t)(t - 1) * N_DIM + my_row;
            out[(size_t)(col0 + 0) * (TMAX * N_DIM) + tb] = xr0;
            out[(size_t)(col0 + 1) * (TMAX * N_DIM) + tb] = xr1;
        }

        float2 acc[8][2];
        #pragma unroll
        for (int i = 0; i < 8; i++) { acc[i][0] = make_float2(0.f, 0.f);
                                      acc[i][1] = make_float2(0.f, 0.f); }

        #pragma unroll
        for (int j = 0; j < 8; j++) {
            // consume prefetched A chunk j
            F4 aCur[4];
            #pragma unroll
            for (int i4 = 0; i4 < 4; i4++) aCur[i4] = pA[i4];

            // prefetch chunk (j+1)&7 — at j==7 this is next STEP's chunk 0
            // (A is loop-invariant, so crossing the barrier is safe)
            {
                const int jn = (j + 1) & 7;
                #pragma unroll
                for (int i4 = 0; i4 < 4; i4++)
                    pA[i4].v = sA[((i4 * 8 + jn) * 8 + w) * 32 + l];
            }

            F4 xa; xa.v = x0p[j * 8 + kl];
            F4 xb; xb.v = x1p[j * 8 + kl];

            #pragma unroll
            for (int i = 0; i < 4; i++) {
                F4 a; a.v = areg[i][j];
                fma2(acc[i][0], a.h[0], xa.h[0]); fma2(acc[i][0], a.h[1], xa.h[1]);
                fma2(acc[i][1], a.h[0], xb.h[0]); fma2(acc[i][1], a.h[1], xb.h[1]);
            }
            #pragma unroll
            for (int i4 = 0; i4 < 4; i4++) {
                fma2(acc[4 + i4][0], aCur[i4].h[0], xa.h[0]);
                fma2(acc[4 + i4][0], aCur[i4].h[1], xa.h[1]);
                fma2(acc[4 + i4][1], aCur[i4].h[0], xb.h[0]);
                fma2(acc[4 + i4][1], aCur[i4].h[1], xb.h[1]);
            }
        }

        float v0[8], v1[8];
        #pragma unroll
        for (int i = 0; i < 8; i++) {
            v0[i] = acc[i][0].x + acc[i][0].y;
            v1[i] = acc[i][1].x + acc[i][1].y;
        }

        float y0 = reduce8(v0, kl) + byv;
        float y1 = reduce8(v1, kl) + byv;

        float xn0 = xr0 + STEP_F * fast_tanh(y0);
        float xn1 = xr1 + STEP_F * fast_tanh(y1);
        xr0 = xn0; xr1 = xn1;

        const int nbuf = buf ^ 1;
        const int pr = permx(my_row);
        sX[(nbuf * 2 + 0) * 256 + pr] = xn0;
        sX[(nbuf * 2 + 1) * 256 + pr] = xn1;

        __syncthreads();
        buf = nbuf;
    }

    // final timestep store (STGs lag one step inside the loop)
    {
        size_t tb = (size_t)(TMAX - 1) * N_DIM + my_row;
        out[(size_t)(col0 + 0) * (TMAX * N_DIM) + tb] = xr0;
        out[(size_t)(col0 + 1) * (TMAX * N_DIM) + tb] = xr1;
    }
}

extern "C" void kernel_launch(void* const* d_in, const int* in_sizes, int n_in,
                              void* d_out, int out_size) {
    const float* X0 = (const float*)d_in[0];
    const float* W  = (const float*)d_in[1];
    const float* by = (const float*)d_in[2];
    float* out = (float*)d_out;

    cudaFuncSetAttribute(antisym_rnn_kernel,
                         cudaFuncAttributeMaxDynamicSharedMemorySize, SMEM_BYTES);
    antisym_rnn_kernel<<<GRID, THREADS, SMEM_BYTES>>>(X0, W, by, out);
}